// round 1
// baseline (speedup 1.0000x reference)
#include <cuda_runtime.h>
#include <cuda_bf16.h>

#define N_DIM 8
#define O_DIM 20
#define P_DIM 20
#define TILE_N 128

// Expanded weight matrices (sample-independent, computed by prep kernel).
__device__ float g_Wm[P_DIM * 7 * O_DIM * O_DIM];        // [p][i][o][q]   56000
__device__ float g_Wv[P_DIM * 6 * 7 * O_DIM * O_DIM];    // [p][k][i][o][q] 336000
__device__ float g_w0m[P_DIM * O_DIM];                   // [p][o]          400
__device__ float g_w0v[P_DIM * 6 * O_DIM];               // [p][k][o]       2400

__constant__ float c_binom[O_DIM] = {
    1.f, 19.f, 171.f, 969.f, 3876.f, 11628.f, 27132.f, 50388.f, 75582.f, 92378.f,
    92378.f, 75582.f, 50388.f, 27132.f, 11628.f, 3876.f, 969.f, 171.f, 19.f, 1.f};

__constant__ float c_cinv[6] = {
    1.0f, 1.0f / 2.0f, 1.0f / 6.0f, 1.0f / 24.0f, 1.0f / 120.0f, 1.0f / 720.0f};

// ---------------------------------------------------------------------------
// Prep: expand exp() weight matrices once per launch (deterministic).
//   meanw  : [7, P, O, O]   meanw0 : [P, 1, O]
//   varw   : [7, P, O, O]   varw0  : [P, 1, O]
// ---------------------------------------------------------------------------
__global__ void prep_kernel(const float* __restrict__ meanw0,
                            const float* __restrict__ meanw,
                            const float* __restrict__ varw0,
                            const float* __restrict__ varw) {
    int idx = blockIdx.x * blockDim.x + threadIdx.x;
    if (idx < 56000) {
        // g_Wm[(p*7 + i)*400 + oq] = exp(meanw[i][p][oq])
        int oq = idx % 400;
        int r = idx / 400;
        int i = r % 7;
        int p = r / 7;
        g_Wm[idx] = expf(meanw[(i * 20 + p) * 400 + oq]);
    } else if (idx < 392000) {
        // g_Wv[((p*6 + k)*7 + i)*400 + oq] = exp(2*m + (k+1)*v)
        int j = idx - 56000;
        int oq = j % 400;
        int r = j / 400;
        int i = r % 7;
        int k = (r / 7) % 6;
        int p = r / 42;
        float m = meanw[(i * 20 + p) * 400 + oq];
        float v = varw[(i * 20 + p) * 400 + oq];
        g_Wv[j] = expf(2.0f * m + (float)(k + 1) * v);
    } else if (idx < 392400) {
        int j = idx - 392000;  // p*20 + o
        g_w0m[j] = expf(meanw0[j]);
    } else if (idx < 394800) {
        int j = idx - 392400;  // (p*6 + k)*20 + o
        int o = j % 20;
        int k = (j / 20) % 6;
        int p = j / 120;
        g_w0v[j] = expf(2.0f * meanw0[p * 20 + o] + (float)(k + 1) * varw0[p * 20 + o]);
    }
}

// ---------------------------------------------------------------------------
// One chain evaluation: f0 = W0 .* B0(^2); f = (f @ W_i) .* B_i(^2); sum(f)
// All f/g state in registers (o,q fully unrolled), W from smem (broadcast),
// basis from smem (lane-contiguous, conflict-free).
// ---------------------------------------------------------------------------
template <bool VAR>
__device__ __forceinline__ float chain_eval(const float* __restrict__ sW,
                                            const float* __restrict__ sW0,
                                            const float* __restrict__ sBt,
                                            const int* __restrict__ pm) {
    float f[O_DIM];
    {
        int d0 = pm[0];
        const float* bb = sBt + d0 * O_DIM * TILE_N;
#pragma unroll
        for (int k = 0; k < O_DIM; ++k) {
            float b = bb[k * TILE_N];
            if (VAR) b *= b;
            f[k] = sW0[k] * b;
        }
    }
#pragma unroll 1
    for (int i = 1; i < N_DIM; ++i) {
        const float* W = sW + (i - 1) * O_DIM * O_DIM;
        int di = pm[i];
        const float* bb = sBt + di * O_DIM * TILE_N;
        float g[O_DIM];
#pragma unroll
        for (int q = 0; q < O_DIM; ++q) g[q] = 0.0f;
#pragma unroll
        for (int o = 0; o < O_DIM; ++o) {
            float fo = f[o];
#pragma unroll
            for (int q = 0; q < O_DIM; ++q) g[q] = fmaf(fo, W[o * O_DIM + q], g[q]);
        }
#pragma unroll
        for (int q = 0; q < O_DIM; ++q) {
            float b = bb[q * TILE_N];
            if (VAR) b *= b;
            f[q] = g[q] * b;
        }
    }
    float s = 0.0f;
#pragma unroll
    for (int k = 0; k < O_DIM; ++k) s += f[k];
    return s;
}

// Dynamic smem layout (floats):
//   sB    [D][O][TILE_N] : 8*20*128 = 20480
//   sW    [7][O][O]      : 2800
//   sW0   [O]            : 20
//   sPerm [P][D] (int)   : 160
#define SMEM_FLOATS (N_DIM * O_DIM * TILE_N + 7 * O_DIM * O_DIM + O_DIM + P_DIM * N_DIM)
#define SMEM_BYTES (SMEM_FLOATS * 4)

__global__ __launch_bounds__(TILE_N, 2) void main_kernel(const float* __restrict__ X,
                                                         const int* __restrict__ perm,
                                                         float* __restrict__ out) {
    extern __shared__ float smem[];
    float* sB = smem;
    float* sW = smem + N_DIM * O_DIM * TILE_N;
    float* sW0 = sW + 7 * O_DIM * O_DIM;
    int* sPerm = (int*)(sW0 + O_DIM);

    const int t = threadIdx.x;
    const int n = blockIdx.x * TILE_N + t;

    for (int j = t; j < P_DIM * N_DIM; j += TILE_N) sPerm[j] = perm[j];

    // Bernstein basis for all 8 dims of this thread's sample -> smem [d][k][t].
    // Stable: b_k = C(19,k) * x^k * (1-x)^(19-k) via separate power chains.
#pragma unroll
    for (int d = 0; d < N_DIM; ++d) {
        float x = X[n * N_DIM + d];
        float omx = 1.0f - x;
        float px[O_DIM];
        px[0] = 1.0f;
#pragma unroll
        for (int k = 1; k < O_DIM; ++k) px[k] = px[k - 1] * x;
        float qk = 1.0f;
#pragma unroll
        for (int k = O_DIM - 1; k >= 0; --k) {
            sB[(d * O_DIM + k) * TILE_N + t] = c_binom[k] * px[k] * qk;
            qk *= omx;
        }
    }
    __syncthreads();

    float mean_acc = 0.0f;
    float var_acc = 0.0f;

#pragma unroll 1
    for (int p = 0; p < P_DIM; ++p) {
#pragma unroll 1
        for (int c = 0; c < 7; ++c) {
            const float* wsrc = (c == 0) ? (g_Wm + p * 2800)
                                         : (g_Wv + (p * 6 + (c - 1)) * 2800);
            const float* w0src = (c == 0) ? (g_w0m + p * O_DIM)
                                          : (g_w0v + (p * 6 + (c - 1)) * O_DIM);
            __syncthreads();  // previous pass done reading sW
#pragma unroll 1
            for (int j = t; j < 700; j += TILE_N) {
                ((float4*)sW)[j] = ((const float4*)wsrc)[j];
            }
            if (t < O_DIM) sW0[t] = w0src[t];
            __syncthreads();  // sW ready

            const int* pm = sPerm + p * N_DIM;
            if (c == 0) {
                mean_acc += chain_eval<false>(sW, sW0, sB + t, pm);
            } else {
                var_acc += chain_eval<true>(sW, sW0, sB + t, pm) * c_cinv[c - 1];
            }
        }
    }

    ((float2*)out)[n] = make_float2(mean_acc, var_acc);
}

extern "C" void kernel_launch(void* const* d_in, const int* in_sizes, int n_in,
                              void* d_out, int out_size) {
    const float* X = (const float*)d_in[0];       // [N, 8]
    const int* perm = (const int*)d_in[1];        // [20, 8]
    const float* meanw0 = (const float*)d_in[2];  // [20, 1, 20]
    const float* meanw = (const float*)d_in[3];   // [7, 20, 20, 20]
    const float* varw0 = (const float*)d_in[4];   // [20, 1, 20]
    const float* varw = (const float*)d_in[5];    // [7, 20, 20, 20]
    float* out = (float*)d_out;                   // [N, 2]

    int N = in_sizes[0] / N_DIM;

    prep_kernel<<<(394800 + 255) / 256, 256>>>(meanw0, meanw, varw0, varw);

    cudaFuncSetAttribute(main_kernel, cudaFuncAttributeMaxDynamicSharedMemorySize,
                         SMEM_BYTES);
    main_kernel<<<N / TILE_N, TILE_N, SMEM_BYTES>>>(X, perm, out);
}

// round 2
// speedup vs baseline: 1.5782x; 1.5782x over previous
#include <cuda_runtime.h>
#include <cuda_bf16.h>

#define N_DIM 8
#define O_DIM 20
#define P_DIM 20
#define NTOT 32768
#define THREADS 128          // samples per CTA = 256 (2 per thread, packed f32x2)

typedef unsigned long long ull;
#define ONE2 0x3F8000003F800000ULL

// Column-scaled weight matrices (binom/cinv folded in by prep).
__device__ float g_Wm[P_DIM * 7 * O_DIM * O_DIM];      // [p][i][o][q]
__device__ float g_Wv[P_DIM * 6 * 7 * O_DIM * O_DIM];  // [p][k][i][o][q]
__device__ float g_w0m[P_DIM * O_DIM];
__device__ float g_w0v[P_DIM * 6 * O_DIM];
// Per-perm partials: [P][N][2] (mean, var)
__device__ float g_scratch[P_DIM * NTOT * 2];

__constant__ float c_binom[O_DIM] = {
    1.f, 19.f, 171.f, 969.f, 3876.f, 11628.f, 27132.f, 50388.f, 75582.f, 92378.f,
    92378.f, 75582.f, 50388.f, 27132.f, 11628.f, 3876.f, 969.f, 171.f, 19.f, 1.f};
__constant__ float c_cinv[6] = {1.0f, 1.f / 2, 1.f / 6, 1.f / 24, 1.f / 120, 1.f / 720};

// ---------------- packed f32x2 helpers ----------------
__device__ __forceinline__ ull fma2(ull a, ull b, ull c) {
    ull d; asm("fma.rn.f32x2 %0, %1, %2, %3;" : "=l"(d) : "l"(a), "l"(b), "l"(c)); return d;
}
__device__ __forceinline__ ull mul2(ull a, ull b) {
    ull d; asm("mul.rn.f32x2 %0, %1, %2;" : "=l"(d) : "l"(a), "l"(b)); return d;
}
__device__ __forceinline__ ull add2(ull a, ull b) {
    ull d; asm("add.rn.f32x2 %0, %1, %2;" : "=l"(d) : "l"(a), "l"(b)); return d;
}
__device__ __forceinline__ ull pack2(float lo, float hi) {
    ull d; asm("mov.b64 %0, {%1, %2};" : "=l"(d) : "f"(lo), "f"(hi)); return d;
}
__device__ __forceinline__ void unpack2(ull v, float& lo, float& hi) {
    asm("mov.b64 {%0, %1}, %2;" : "=f"(lo), "=f"(hi) : "l"(v));
}

// ---------------------------------------------------------------------------
// Prep: W' = exp(...) column-scaled by binom[q]^(1 or 2); cinv folded into w0v.
// meanw/varw: [7, P, O, O]; meanw0/varw0: [P, 1, O]
// ---------------------------------------------------------------------------
__global__ void prep_kernel(const float* __restrict__ meanw0,
                            const float* __restrict__ meanw,
                            const float* __restrict__ varw0,
                            const float* __restrict__ varw) {
    int idx = blockIdx.x * blockDim.x + threadIdx.x;
    if (idx < 56000) {
        int oq = idx % 400;  int q = oq % 20;
        int r = idx / 400;   int i = r % 7;  int p = r / 7;
        g_Wm[idx] = expf(meanw[(i * 20 + p) * 400 + oq]) * c_binom[q];
    } else if (idx < 392000) {
        int j = idx - 56000;
        int oq = j % 400;  int q = oq % 20;
        int r = j / 400;   int i = r % 7;  int k = (r / 7) % 6;  int p = r / 42;
        float m = meanw[(i * 20 + p) * 400 + oq];
        float v = varw[(i * 20 + p) * 400 + oq];
        g_Wv[j] = expf(2.0f * m + (float)(k + 1) * v) * c_binom[q] * c_binom[q];
    } else if (idx < 392400) {
        int j = idx - 392000;  int q = j % 20;
        g_w0m[j] = expf(meanw0[j]) * c_binom[q];
    } else if (idx < 394800) {
        int j = idx - 392400;
        int q = j % 20;  int k = (j / 20) % 6;  int p = j / 120;
        g_w0v[j] = expf(2.0f * meanw0[p * 20 + q] + (float)(k + 1) * varw0[p * 20 + q]) *
                   c_binom[q] * c_binom[q] * c_cinv[k];
    }
}

// ---------------------------------------------------------------------------
// One packed chain: f0 = w0 .* t0;  f = (f @ W_i) .* t_i;  return sum(f).
// t[q] = x^q (1-x)^(19-q) (VAR: with x->x^2, (1-x)->(1-x)^2). binom folded in W.
// ---------------------------------------------------------------------------
template <bool VAR>
__device__ __forceinline__ ull chain_eval(const ulonglong2* __restrict__ sW2,
                                          const ull* __restrict__ sW02,
                                          const ull* __restrict__ sXx,
                                          const ull* __restrict__ sXomx,
                                          const int* __restrict__ sPerm, int t) {
    ull f[20];
    {
        const int d0 = sPerm[0];
        const ull x = sXx[d0 * THREADS + t];
        const ull omx = sXomx[d0 * THREADS + t];
        ull qk[20];
        qk[19] = ONE2;
#pragma unroll
        for (int k = 18; k >= 0; --k) qk[k] = mul2(qk[k + 1], omx);
        ull px = ONE2;
        f[0] = mul2(sW02[0], qk[0]);
#pragma unroll
        for (int q = 1; q < 20; ++q) {
            px = mul2(px, x);
            f[q] = mul2(sW02[q], mul2(px, qk[q]));
        }
    }
#pragma unroll 1
    for (int i = 1; i < N_DIM; ++i) {
        const int di = sPerm[i];
        const ull x = sXx[di * THREADS + t];
        const ull omx = sXomx[di * THREADS + t];
        ull g[20];
#pragma unroll
        for (int q = 0; q < 20; ++q) g[q] = 0ULL;
        const ulonglong2* wbase = sW2 + (i - 1) * 200;
#pragma unroll
        for (int o = 0; o < 20; ++o) {
            const ull fo = f[o];
            const ulonglong2* wr = wbase + o * 10;
#pragma unroll
            for (int j = 0; j < 10; ++j) {
                ulonglong2 w = wr[j];
                g[2 * j]     = fma2(fo, w.x, g[2 * j]);
                g[2 * j + 1] = fma2(fo, w.y, g[2 * j + 1]);
            }
        }
        ull qk[20];
        qk[19] = ONE2;
#pragma unroll
        for (int k = 18; k >= 0; --k) qk[k] = mul2(qk[k + 1], omx);
        ull px = ONE2;
        f[0] = mul2(g[0], qk[0]);
#pragma unroll
        for (int q = 1; q < 20; ++q) {
            px = mul2(px, x);
            f[q] = mul2(g[q], mul2(px, qk[q]));
        }
    }
    ull s = f[0];
#pragma unroll
    for (int q = 1; q < 20; ++q) s = add2(s, f[q]);
    return s;
}

// Dynamic smem (bytes):
//   sW2   : 7*400 duplicated pairs = 5600 floats         = 22400
//   sXx/sXomx/sXxx/sXomxx : 4 * [8][128] ull             = 32768
//   sW02  : 20 ull                                       = 160
//   sPerm : 8 int                                        = 32
#define SMEM_BYTES (22400 + 32768 + 160 + 32)

__global__ __launch_bounds__(THREADS, 3) void main_kernel(const float* __restrict__ X,
                                                          const int* __restrict__ perm,
                                                          int ntiles) {
    extern __shared__ char smem[];
    ulonglong2* sW2 = (ulonglong2*)smem;                   // 22400 B
    ull* sXx = (ull*)(smem + 22400);                       // [8][128]
    ull* sXomx = sXx + 8 * THREADS;
    ull* sXxx = sXomx + 8 * THREADS;
    ull* sXomxx = sXxx + 8 * THREADS;
    ull* sW02 = sXomxx + 8 * THREADS;                      // 20 ull
    int* sPerm = (int*)(sW02 + 20);

    const int t = threadIdx.x;
    const int tile = blockIdx.x % ntiles;
    const int p = blockIdx.x / ntiles;
    const int nA = (tile * THREADS + t) * 2;               // this thread's sample pair

    if (t < N_DIM) sPerm[t] = perm[p * N_DIM + t];

    // Load the two samples' x vectors, build packed x/omx and squares in smem.
    {
        const float4* XA = (const float4*)(X + nA * N_DIM);
        float4 a0 = XA[0], a1 = XA[1], b0 = XA[2], b1 = XA[3];
        float xa[8] = {a0.x, a0.y, a0.z, a0.w, a1.x, a1.y, a1.z, a1.w};
        float xb[8] = {b0.x, b0.y, b0.z, b0.w, b1.x, b1.y, b1.z, b1.w};
#pragma unroll
        for (int d = 0; d < N_DIM; ++d) {
            float oa = 1.0f - xa[d], ob = 1.0f - xb[d];
            sXx[d * THREADS + t] = pack2(xa[d], xb[d]);
            sXomx[d * THREADS + t] = pack2(oa, ob);
            sXxx[d * THREADS + t] = pack2(xa[d] * xa[d], xb[d] * xb[d]);
            sXomxx[d * THREADS + t] = pack2(oa * oa, ob * ob);
        }
    }

    ull mean2 = 0ULL, var2 = 0ULL;

#pragma unroll 1
    for (int c = 0; c < 7; ++c) {
        const float* wsrc = (c == 0) ? (g_Wm + p * 2800)
                                     : (g_Wv + (p * 6 + (c - 1)) * 2800);
        const float* w0src = (c == 0) ? (g_w0m + p * O_DIM)
                                      : (g_w0v + (p * 6 + (c - 1)) * O_DIM);
        __syncthreads();  // previous chain done reading sW2
        const float4* src4 = (const float4*)wsrc;
        float4* dst4 = (float4*)sW2;
#pragma unroll 1
        for (int j = t; j < 700; j += THREADS) {
            float4 v = src4[j];
            dst4[2 * j]     = make_float4(v.x, v.x, v.y, v.y);
            dst4[2 * j + 1] = make_float4(v.z, v.z, v.w, v.w);
        }
        if (t < O_DIM) {
            float w = w0src[t];
            sW02[t] = pack2(w, w);
        }
        __syncthreads();

        if (c == 0) {
            mean2 = chain_eval<false>(sW2, sW02, sXx, sXomx, sPerm, t);
        } else {
            var2 = add2(var2, chain_eval<true>(sW2, sW02, sXxx, sXomxx, sPerm, t));
        }
    }

    float mA, mB, vA, vB;
    unpack2(mean2, mA, mB);
    unpack2(var2, vA, vB);
    // scratch[p][n][2]; nA even -> 16B aligned float4 store of 2 samples.
    float4* out4 = (float4*)(g_scratch + ((size_t)p * NTOT + nA) * 2);
    *out4 = make_float4(mA, vA, mB, vB);
}

__global__ void reduce_kernel(float* __restrict__ out, int n) {
    int i = blockIdx.x * blockDim.x + threadIdx.x;
    if (i >= n) return;
    float m = 0.0f, v = 0.0f;
#pragma unroll
    for (int p = 0; p < P_DIM; ++p) {
        const float2 s = *(const float2*)(g_scratch + ((size_t)p * NTOT + i) * 2);
        m += s.x;
        v += s.y;
    }
    ((float2*)out)[i] = make_float2(m, v);
}

extern "C" void kernel_launch(void* const* d_in, const int* in_sizes, int n_in,
                              void* d_out, int out_size) {
    const float* X = (const float*)d_in[0];       // [N, 8]
    const int* perm = (const int*)d_in[1];        // [20, 8]
    const float* meanw0 = (const float*)d_in[2];  // [20, 1, 20]
    const float* meanw = (const float*)d_in[3];   // [7, 20, 20, 20]
    const float* varw0 = (const float*)d_in[4];   // [20, 1, 20]
    const float* varw = (const float*)d_in[5];    // [7, 20, 20, 20]
    float* out = (float*)d_out;                   // [N, 2]

    int N = in_sizes[0] / N_DIM;
    int ntiles = N / (2 * THREADS);               // 128 for N=32768

    prep_kernel<<<(394800 + 255) / 256, 256>>>(meanw0, meanw, varw0, varw);

    cudaFuncSetAttribute(main_kernel, cudaFuncAttributeMaxDynamicSharedMemorySize,
                         SMEM_BYTES);
    main_kernel<<<P_DIM * ntiles, THREADS, SMEM_BYTES>>>(X, perm, ntiles);

    reduce_kernel<<<(N + 255) / 256, 256>>>(out, N);
}

// round 3
// speedup vs baseline: 1.9685x; 1.2473x over previous
#include <cuda_runtime.h>
#include <cuda_bf16.h>

#define N_DIM 8
#define O_DIM 20
#define P_DIM 20
#define NTOT 32768
#define THREADS 128   // 4 samples per thread (2 packed f32x2 pairs) -> 512 samples/CTA

typedef unsigned long long ull;
#define ONE2 0x3F8000003F800000ULL

// Column-scaled weight matrices (binom/cinv folded in by prep).
__device__ float g_Wm[P_DIM * 7 * O_DIM * O_DIM];      // [p][i][o][q]
__device__ float g_Wv[P_DIM * 6 * 7 * O_DIM * O_DIM];  // [p][k][i][o][q]
__device__ float g_w0m[P_DIM * O_DIM];
__device__ float g_w0v[P_DIM * 6 * O_DIM];
// Per-perm partials: [P][N][2] (mean, var)
__device__ float g_scratch[P_DIM * NTOT * 2];

__constant__ float c_binom[O_DIM] = {
    1.f, 19.f, 171.f, 969.f, 3876.f, 11628.f, 27132.f, 50388.f, 75582.f, 92378.f,
    92378.f, 75582.f, 50388.f, 27132.f, 11628.f, 3876.f, 969.f, 171.f, 19.f, 1.f};
__constant__ float c_cinv[6] = {1.0f, 1.f / 2, 1.f / 6, 1.f / 24, 1.f / 120, 1.f / 720};

// ---------------- packed f32x2 helpers ----------------
__device__ __forceinline__ ull fma2(ull a, ull b, ull c) {
    ull d; asm("fma.rn.f32x2 %0, %1, %2, %3;" : "=l"(d) : "l"(a), "l"(b), "l"(c)); return d;
}
__device__ __forceinline__ ull mul2(ull a, ull b) {
    ull d; asm("mul.rn.f32x2 %0, %1, %2;" : "=l"(d) : "l"(a), "l"(b)); return d;
}
__device__ __forceinline__ ull add2(ull a, ull b) {
    ull d; asm("add.rn.f32x2 %0, %1, %2;" : "=l"(d) : "l"(a), "l"(b)); return d;
}
__device__ __forceinline__ ull pack2(float lo, float hi) {
    ull d; asm("mov.b64 %0, {%1, %2};" : "=l"(d) : "f"(lo), "f"(hi)); return d;
}
__device__ __forceinline__ void unpack2(ull v, float& lo, float& hi) {
    asm("mov.b64 {%0, %1}, %2;" : "=f"(lo), "=f"(hi) : "l"(v));
}

// ---------------------------------------------------------------------------
// Prep: W' = exp(...) column-scaled by binom[q]^(1 or 2); cinv folded into w0v.
// ---------------------------------------------------------------------------
__global__ void prep_kernel(const float* __restrict__ meanw0,
                            const float* __restrict__ meanw,
                            const float* __restrict__ varw0,
                            const float* __restrict__ varw) {
    int idx = blockIdx.x * blockDim.x + threadIdx.x;
    if (idx < 56000) {
        int oq = idx % 400;  int q = oq % 20;
        int r = idx / 400;   int i = r % 7;  int p = r / 7;
        g_Wm[idx] = expf(meanw[(i * 20 + p) * 400 + oq]) * c_binom[q];
    } else if (idx < 392000) {
        int j = idx - 56000;
        int oq = j % 400;  int q = oq % 20;
        int r = j / 400;   int i = r % 7;  int k = (r / 7) % 6;  int p = r / 42;
        float m = meanw[(i * 20 + p) * 400 + oq];
        float v = varw[(i * 20 + p) * 400 + oq];
        g_Wv[j] = expf(2.0f * m + (float)(k + 1) * v) * c_binom[q] * c_binom[q];
    } else if (idx < 392400) {
        int j = idx - 392000;  int q = j % 20;
        g_w0m[j] = expf(meanw0[j]) * c_binom[q];
    } else if (idx < 394800) {
        int j = idx - 392400;
        int q = j % 20;  int k = (j / 20) % 6;  int p = j / 120;
        g_w0v[j] = expf(2.0f * meanw0[p * 20 + q] + (float)(k + 1) * varw0[p * 20 + q]) *
                   c_binom[q] * c_binom[q] * c_cinv[k];
    }
}

// ---------------------------------------------------------------------------
// Two packed sample-pairs per thread through one chain.
// t[q] = x^q (1-x)^(19-q) applied via two running-product passes.
// Returns the two packed sums via out1/out2 (accumulated).
// ---------------------------------------------------------------------------
template <bool VAR>
__device__ __forceinline__ void chain_eval(const ulonglong2* __restrict__ sW2,
                                           const ull* __restrict__ sW02,
                                           const ull* __restrict__ sXx,
                                           const ull* __restrict__ sXomx,
                                           const int* __restrict__ sPerm, int t,
                                           ull& out1, ull& out2, ull cscale) {
    ull f1[O_DIM], f2[O_DIM];
    // ---- initial step: f = w0 .* t(d0) ----
    {
        const int d0 = sPerm[0];
        const ull x1 = sXx[(d0 * 2 + 0) * THREADS + t];
        const ull x2 = sXx[(d0 * 2 + 1) * THREADS + t];
        const ull o1 = sXomx[(d0 * 2 + 0) * THREADS + t];
        const ull o2 = sXomx[(d0 * 2 + 1) * THREADS + t];
        ull px1 = ONE2, px2 = ONE2;
        f1[0] = sW02[0]; f2[0] = sW02[0];
#pragma unroll
        for (int q = 1; q < O_DIM; ++q) {
            px1 = mul2(px1, x1); px2 = mul2(px2, x2);
            f1[q] = mul2(sW02[q], px1);
            f2[q] = mul2(sW02[q], px2);
        }
        ull qk1 = ONE2, qk2 = ONE2;
#pragma unroll
        for (int q = O_DIM - 2; q >= 0; --q) {
            qk1 = mul2(qk1, o1); qk2 = mul2(qk2, o2);
            f1[q] = mul2(f1[q], qk1);
            f2[q] = mul2(f2[q], qk2);
        }
    }
#pragma unroll 1
    for (int i = 1; i < N_DIM; ++i) {
        const int di = sPerm[i];
        const ull x1 = sXx[(di * 2 + 0) * THREADS + t];
        const ull x2 = sXx[(di * 2 + 1) * THREADS + t];
        const ull o1 = sXomx[(di * 2 + 0) * THREADS + t];
        const ull o2 = sXomx[(di * 2 + 1) * THREADS + t];
        ull g1[O_DIM], g2[O_DIM];
#pragma unroll
        for (int q = 0; q < O_DIM; ++q) { g1[q] = 0ULL; g2[q] = 0ULL; }
        const ulonglong2* wbase = sW2 + (i - 1) * 200;
#pragma unroll
        for (int o = 0; o < O_DIM; ++o) {
            const ull a1 = f1[o];
            const ull a2 = f2[o];
            const ulonglong2* wr = wbase + o * 10;
#pragma unroll
            for (int j = 0; j < 10; ++j) {
                ulonglong2 w = wr[j];   // (w2q,w2q | w2q+1,w2q+1) duplicated
                g1[2 * j]     = fma2(a1, w.x, g1[2 * j]);
                g2[2 * j]     = fma2(a2, w.x, g2[2 * j]);
                g1[2 * j + 1] = fma2(a1, w.y, g1[2 * j + 1]);
                g2[2 * j + 1] = fma2(a2, w.y, g2[2 * j + 1]);
            }
        }
        // gating: f[q] = g[q] * x^q * (1-x)^(19-q), running products
        ull px1 = ONE2, px2 = ONE2;
        f1[0] = g1[0]; f2[0] = g2[0];
#pragma unroll
        for (int q = 1; q < O_DIM; ++q) {
            px1 = mul2(px1, x1); px2 = mul2(px2, x2);
            f1[q] = mul2(g1[q], px1);
            f2[q] = mul2(g2[q], px2);
        }
        ull qk1 = ONE2, qk2 = ONE2;
#pragma unroll
        for (int q = O_DIM - 2; q >= 0; --q) {
            qk1 = mul2(qk1, o1); qk2 = mul2(qk2, o2);
            f1[q] = mul2(f1[q], qk1);
            f2[q] = mul2(f2[q], qk2);
        }
    }
    ull s1 = f1[0], s2 = f2[0];
#pragma unroll
    for (int q = 1; q < O_DIM; ++q) { s1 = add2(s1, f1[q]); s2 = add2(s2, f2[q]); }
    out1 = fma2(s1, cscale, out1);
    out2 = fma2(s2, cscale, out2);
}

// Dynamic smem (bytes):
//   sW2   : 7*200 ulonglong2 (duplicated)        = 22400
//   sXx / sXomx : [8][2][128] ull each, x2 sets (plain + squared) = 65536
//   sW02  : 20 ull                               = 160
//   sPerm : 8 int                                = 32
#define SMEM_BYTES (22400 + 65536 + 160 + 32)

__global__ __launch_bounds__(THREADS, 2) void main_kernel(const float* __restrict__ X,
                                                          const int* __restrict__ perm,
                                                          int ntiles) {
    extern __shared__ char smem[];
    ulonglong2* sW2 = (ulonglong2*)smem;                   // 22400 B
    ull* sXx = (ull*)(smem + 22400);                       // [8][2][128]
    ull* sXomx = sXx + 8 * 2 * THREADS;
    ull* sXxx = sXomx + 8 * 2 * THREADS;
    ull* sXomxx = sXxx + 8 * 2 * THREADS;
    ull* sW02 = sXomxx + 8 * 2 * THREADS;                  // 20 ull
    int* sPerm = (int*)(sW02 + O_DIM);

    const int t = threadIdx.x;
    const int tile = blockIdx.x % ntiles;
    const int p = blockIdx.x / ntiles;
    const int nA = (tile * THREADS + t) * 4;               // 4 consecutive samples

    if (t < N_DIM) sPerm[t] = perm[p * N_DIM + t];

    // Load 4 samples' x vectors; build packed (x, omx) + squares in smem.
    {
        const float4* XA = (const float4*)(X + (size_t)nA * N_DIM);
        float xs[4][8];
#pragma unroll
        for (int s = 0; s < 4; ++s) {
            float4 a = XA[2 * s], b = XA[2 * s + 1];
            xs[s][0] = a.x; xs[s][1] = a.y; xs[s][2] = a.z; xs[s][3] = a.w;
            xs[s][4] = b.x; xs[s][5] = b.y; xs[s][6] = b.z; xs[s][7] = b.w;
        }
#pragma unroll
        for (int d = 0; d < N_DIM; ++d) {
#pragma unroll
            for (int pr = 0; pr < 2; ++pr) {
                float xa = xs[2 * pr][d], xb = xs[2 * pr + 1][d];
                float oa = 1.0f - xa, ob = 1.0f - xb;
                int idx = (d * 2 + pr) * THREADS + t;
                sXx[idx] = pack2(xa, xb);
                sXomx[idx] = pack2(oa, ob);
                sXxx[idx] = pack2(xa * xa, xb * xb);
                sXomxx[idx] = pack2(oa * oa, ob * ob);
            }
        }
    }

    ull mean1 = 0ULL, mean2 = 0ULL, var1 = 0ULL, var2 = 0ULL;

#pragma unroll 1
    for (int c = 0; c < 7; ++c) {
        const float* wsrc = (c == 0) ? (g_Wm + p * 2800)
                                     : (g_Wv + (p * 6 + (c - 1)) * 2800);
        const float* w0src = (c == 0) ? (g_w0m + p * O_DIM)
                                      : (g_w0v + (p * 6 + (c - 1)) * O_DIM);
        __syncthreads();  // previous chain done reading sW2
        const float4* src4 = (const float4*)wsrc;
        float4* dst4 = (float4*)sW2;
#pragma unroll 1
        for (int j = t; j < 700; j += THREADS) {
            float4 v = src4[j];
            dst4[2 * j]     = make_float4(v.x, v.x, v.y, v.y);
            dst4[2 * j + 1] = make_float4(v.z, v.z, v.w, v.w);
        }
        if (t < O_DIM) {
            float w = w0src[t];
            sW02[t] = pack2(w, w);
        }
        __syncthreads();

        if (c == 0) {
            chain_eval<false>(sW2, sW02, sXx, sXomx, sPerm, t, mean1, mean2, ONE2);
        } else {
            chain_eval<true>(sW2, sW02, sXxx, sXomxx, sPerm, t, var1, var2, ONE2);
        }
    }

    float m0, m1, m2, m3, v0, v1, v2, v3;
    unpack2(mean1, m0, m1); unpack2(mean2, m2, m3);
    unpack2(var1, v0, v1);  unpack2(var2, v2, v3);
    float4* out4 = (float4*)(g_scratch + ((size_t)p * NTOT + nA) * 2);
    out4[0] = make_float4(m0, v0, m1, v1);
    out4[1] = make_float4(m2, v2, m3, v3);
}

__global__ void reduce_kernel(float* __restrict__ out, int n) {
    int i = blockIdx.x * blockDim.x + threadIdx.x;
    if (i >= n) return;
    float m = 0.0f, v = 0.0f;
#pragma unroll
    for (int p = 0; p < P_DIM; ++p) {
        const float2 s = *(const float2*)(g_scratch + ((size_t)p * NTOT + i) * 2);
        m += s.x;
        v += s.y;
    }
    ((float2*)out)[i] = make_float2(m, v);
}

extern "C" void kernel_launch(void* const* d_in, const int* in_sizes, int n_in,
                              void* d_out, int out_size) {
    const float* X = (const float*)d_in[0];       // [N, 8]
    const int* perm = (const int*)d_in[1];        // [20, 8]
    const float* meanw0 = (const float*)d_in[2];  // [20, 1, 20]
    const float* meanw = (const float*)d_in[3];   // [7, 20, 20, 20]
    const float* varw0 = (const float*)d_in[4];   // [20, 1, 20]
    const float* varw = (const float*)d_in[5];    // [7, 20, 20, 20]
    float* out = (float*)d_out;                   // [N, 2]

    int N = in_sizes[0] / N_DIM;
    int ntiles = N / (4 * THREADS);               // 64 for N=32768

    prep_kernel<<<(394800 + 255) / 256, 256>>>(meanw0, meanw, varw0, varw);

    cudaFuncSetAttribute(main_kernel, cudaFuncAttributeMaxDynamicSharedMemorySize,
                         SMEM_BYTES);
    main_kernel<<<P_DIM * ntiles, THREADS, SMEM_BYTES>>>(X, perm, ntiles);

    reduce_kernel<<<(N + 255) / 256, 256>>>(out, N);
}

// round 4
// speedup vs baseline: 2.0556x; 1.0442x over previous
#include <cuda_runtime.h>
#include <cuda_bf16.h>

#define N_DIM 8
#define O_DIM 20
#define P_DIM 20
#define NTOT 32768
#define THREADS 128   // 4 samples/thread (2 packed f32x2 pairs) -> 512 samples/CTA

typedef unsigned long long ull;
#define ONE2 0x3F8000003F800000ULL

// Column-scaled weight matrices (binom/cinv folded in by prep).
__device__ float g_Wm[P_DIM * 7 * O_DIM * O_DIM];      // [p][i][o][q]
__device__ float g_Wv[P_DIM * 6 * 7 * O_DIM * O_DIM];  // [p][k][i][o][q]
__device__ float g_w0m[P_DIM * O_DIM];
__device__ float g_w0v[P_DIM * 6 * O_DIM];
// Per-(perm,chain) partial sums: [P*7][N]
__device__ float g_scratch[P_DIM * 7 * NTOT];

__constant__ float c_binom[O_DIM] = {
    1.f, 19.f, 171.f, 969.f, 3876.f, 11628.f, 27132.f, 50388.f, 75582.f, 92378.f,
    92378.f, 75582.f, 50388.f, 27132.f, 11628.f, 3876.f, 969.f, 171.f, 19.f, 1.f};
__constant__ float c_cinv[6] = {1.0f, 1.f / 2, 1.f / 6, 1.f / 24, 1.f / 120, 1.f / 720};

// ---------------- packed f32x2 helpers ----------------
__device__ __forceinline__ ull fma2(ull a, ull b, ull c) {
    ull d; asm("fma.rn.f32x2 %0, %1, %2, %3;" : "=l"(d) : "l"(a), "l"(b), "l"(c)); return d;
}
__device__ __forceinline__ ull mul2(ull a, ull b) {
    ull d; asm("mul.rn.f32x2 %0, %1, %2;" : "=l"(d) : "l"(a), "l"(b)); return d;
}
__device__ __forceinline__ ull add2(ull a, ull b) {
    ull d; asm("add.rn.f32x2 %0, %1, %2;" : "=l"(d) : "l"(a), "l"(b)); return d;
}
__device__ __forceinline__ ull pack2(float lo, float hi) {
    ull d; asm("mov.b64 %0, {%1, %2};" : "=l"(d) : "f"(lo), "f"(hi)); return d;
}
__device__ __forceinline__ void unpack2(ull v, float& lo, float& hi) {
    asm("mov.b64 {%0, %1}, %2;" : "=f"(lo), "=f"(hi) : "l"(v));
}

// ---------------------------------------------------------------------------
// Prep: W' = exp(...) column-scaled by binom[q]^(1 or 2); cinv folded into w0v.
// ---------------------------------------------------------------------------
__global__ void prep_kernel(const float* __restrict__ meanw0,
                            const float* __restrict__ meanw,
                            const float* __restrict__ varw0,
                            const float* __restrict__ varw) {
    int idx = blockIdx.x * blockDim.x + threadIdx.x;
    if (idx < 56000) {
        int oq = idx % 400;  int q = oq % 20;
        int r = idx / 400;   int i = r % 7;  int p = r / 7;
        g_Wm[idx] = expf(meanw[(i * 20 + p) * 400 + oq]) * c_binom[q];
    } else if (idx < 392000) {
        int j = idx - 56000;
        int oq = j % 400;  int q = oq % 20;
        int r = j / 400;   int i = r % 7;  int k = (r / 7) % 6;  int p = r / 42;
        float m = meanw[(i * 20 + p) * 400 + oq];
        float v = varw[(i * 20 + p) * 400 + oq];
        g_Wv[j] = expf(2.0f * m + (float)(k + 1) * v) * c_binom[q] * c_binom[q];
    } else if (idx < 392400) {
        int j = idx - 392000;  int q = j % 20;
        g_w0m[j] = expf(meanw0[j]) * c_binom[q];
    } else if (idx < 394800) {
        int j = idx - 392400;
        int q = j % 20;  int k = (j / 20) % 6;  int p = j / 120;
        g_w0v[j] = expf(2.0f * meanw0[p * 20 + q] + (float)(k + 1) * varw0[p * 20 + q]) *
                   c_binom[q] * c_binom[q] * c_cinv[k];
    }
}

// Dynamic smem (bytes):
//   sW2   : 7*200 ulonglong2 (duplicated pairs)  = 22400
//   sXx / sXomx : [8][2][128] ull each           = 16384 * 2
//   sW02  : 20 ull                               = 160
//   sPerm : 8 int                                = 32
#define SMEM_BYTES (22400 + 32768 + 160 + 32)

// One CTA = one (perm p, chain c) over a 512-sample tile.
__global__ __launch_bounds__(THREADS, 2) void main_kernel(const float* __restrict__ X,
                                                          const int* __restrict__ perm,
                                                          int ntiles) {
    extern __shared__ char smem[];
    ulonglong2* sW2 = (ulonglong2*)smem;                   // 22400 B
    ull* sXx = (ull*)(smem + 22400);                       // [8][2][128]
    ull* sXomx = sXx + 8 * 2 * THREADS;
    ull* sW02 = sXomx + 8 * 2 * THREADS;                   // 20 ull
    int* sPerm = (int*)(sW02 + O_DIM);

    const int t = threadIdx.x;
    const int tile = blockIdx.x % ntiles;
    const int pc = blockIdx.x / ntiles;                    // p*7 + c
    const int p = pc / 7;
    const int c = pc % 7;
    const int nA = (tile * THREADS + t) * 4;               // 4 consecutive samples

    if (t < N_DIM) sPerm[t] = perm[p * N_DIM + t];

    // ---- stage W (duplicated (w,w) pairs) and w0 ----
    {
        const float* wsrc = (c == 0) ? (g_Wm + p * 2800)
                                     : (g_Wv + (p * 6 + (c - 1)) * 2800);
        const float* w0src = (c == 0) ? (g_w0m + p * O_DIM)
                                      : (g_w0v + (p * 6 + (c - 1)) * O_DIM);
        const float4* src4 = (const float4*)wsrc;
        float4* dst4 = (float4*)sW2;
#pragma unroll 1
        for (int j = t; j < 700; j += THREADS) {
            float4 v = src4[j];
            dst4[2 * j]     = make_float4(v.x, v.x, v.y, v.y);
            dst4[2 * j + 1] = make_float4(v.z, v.z, v.w, v.w);
        }
        if (t < O_DIM) {
            float w = w0src[t];
            sW02[t] = pack2(w, w);
        }
    }

    // ---- stage gates: (x, 1-x), squared for variance chains (c > 0) ----
    {
        const float4* XA = (const float4*)(X + (size_t)nA * N_DIM);
        float xs[4][8];
#pragma unroll
        for (int s = 0; s < 4; ++s) {
            float4 a = XA[2 * s], b = XA[2 * s + 1];
            xs[s][0] = a.x; xs[s][1] = a.y; xs[s][2] = a.z; xs[s][3] = a.w;
            xs[s][4] = b.x; xs[s][5] = b.y; xs[s][6] = b.z; xs[s][7] = b.w;
        }
        const bool sq = (c != 0);
#pragma unroll
        for (int d = 0; d < N_DIM; ++d) {
#pragma unroll
            for (int pr = 0; pr < 2; ++pr) {
                float xa = xs[2 * pr][d], xb = xs[2 * pr + 1][d];
                float oa = 1.0f - xa, ob = 1.0f - xb;
                if (sq) { xa *= xa; xb *= xb; oa *= oa; ob *= ob; }
                int idx = (d * 2 + pr) * THREADS + t;
                sXx[idx] = pack2(xa, xb);
                sXomx[idx] = pack2(oa, ob);
            }
        }
    }
    __syncthreads();

    // ---- the chain ----
    ull f1[O_DIM], f2[O_DIM];
    {
        const int d0 = sPerm[0];
        const ull x1 = sXx[(d0 * 2 + 0) * THREADS + t];
        const ull x2 = sXx[(d0 * 2 + 1) * THREADS + t];
        const ull o1 = sXomx[(d0 * 2 + 0) * THREADS + t];
        const ull o2 = sXomx[(d0 * 2 + 1) * THREADS + t];
        ull px1 = ONE2, px2 = ONE2;
        f1[0] = sW02[0]; f2[0] = sW02[0];
#pragma unroll
        for (int q = 1; q < O_DIM; ++q) {
            px1 = mul2(px1, x1); px2 = mul2(px2, x2);
            f1[q] = mul2(sW02[q], px1);
            f2[q] = mul2(sW02[q], px2);
        }
        ull qk1 = ONE2, qk2 = ONE2;
#pragma unroll
        for (int q = O_DIM - 2; q >= 0; --q) {
            qk1 = mul2(qk1, o1); qk2 = mul2(qk2, o2);
            f1[q] = mul2(f1[q], qk1);
            f2[q] = mul2(f2[q], qk2);
        }
    }
#pragma unroll 1
    for (int i = 1; i < N_DIM; ++i) {
        const int di = sPerm[i];
        const ull x1 = sXx[(di * 2 + 0) * THREADS + t];
        const ull x2 = sXx[(di * 2 + 1) * THREADS + t];
        const ull o1 = sXomx[(di * 2 + 0) * THREADS + t];
        const ull o2 = sXomx[(di * 2 + 1) * THREADS + t];
        ull g1[O_DIM], g2[O_DIM];
#pragma unroll
        for (int q = 0; q < O_DIM; ++q) { g1[q] = 0ULL; g2[q] = 0ULL; }
        const ulonglong2* wbase = sW2 + (i - 1) * 200;
#pragma unroll
        for (int o = 0; o < O_DIM; ++o) {
            const ull a1 = f1[o];
            const ull a2 = f2[o];
            const ulonglong2* wr = wbase + o * 10;
#pragma unroll
            for (int j = 0; j < 10; ++j) {
                ulonglong2 w = wr[j];   // (w2q,w2q | w2q+1,w2q+1) duplicated
                g1[2 * j]     = fma2(a1, w.x, g1[2 * j]);
                g2[2 * j]     = fma2(a2, w.x, g2[2 * j]);
                g1[2 * j + 1] = fma2(a1, w.y, g1[2 * j + 1]);
                g2[2 * j + 1] = fma2(a2, w.y, g2[2 * j + 1]);
            }
        }
        ull px1 = ONE2, px2 = ONE2;
        f1[0] = g1[0]; f2[0] = g2[0];
#pragma unroll
        for (int q = 1; q < O_DIM; ++q) {
            px1 = mul2(px1, x1); px2 = mul2(px2, x2);
            f1[q] = mul2(g1[q], px1);
            f2[q] = mul2(g2[q], px2);
        }
        ull qk1 = ONE2, qk2 = ONE2;
#pragma unroll
        for (int q = O_DIM - 2; q >= 0; --q) {
            qk1 = mul2(qk1, o1); qk2 = mul2(qk2, o2);
            f1[q] = mul2(f1[q], qk1);
            f2[q] = mul2(f2[q], qk2);
        }
    }
    // Tree sum (log depth).
#pragma unroll
    for (int stride = 1; stride < O_DIM; stride *= 2) {
#pragma unroll
        for (int q = 0; q + stride < O_DIM; q += 2 * stride) {
            f1[q] = add2(f1[q], f1[q + stride]);
            f2[q] = add2(f2[q], f2[q + stride]);
        }
    }
    float s0, s1, s2, s3;
    unpack2(f1[0], s0, s1);
    unpack2(f2[0], s2, s3);
    *(float4*)(g_scratch + (size_t)pc * NTOT + nA) = make_float4(s0, s1, s2, s3);
}

__global__ void reduce_kernel(float* __restrict__ out, int n) {
    int i = blockIdx.x * blockDim.x + threadIdx.x;
    if (i >= n) return;
    float m = 0.0f, v = 0.0f;
#pragma unroll
    for (int p = 0; p < P_DIM; ++p) {
        m += g_scratch[(size_t)(p * 7) * NTOT + i];
#pragma unroll
        for (int c = 1; c < 7; ++c)
            v += g_scratch[(size_t)(p * 7 + c) * NTOT + i];
    }
    ((float2*)out)[i] = make_float2(m, v);
}

extern "C" void kernel_launch(void* const* d_in, const int* in_sizes, int n_in,
                              void* d_out, int out_size) {
    const float* X = (const float*)d_in[0];       // [N, 8]
    const int* perm = (const int*)d_in[1];        // [20, 8]
    const float* meanw0 = (const float*)d_in[2];  // [20, 1, 20]
    const float* meanw = (const float*)d_in[3];   // [7, 20, 20, 20]
    const float* varw0 = (const float*)d_in[4];   // [20, 1, 20]
    const float* varw = (const float*)d_in[5];    // [7, 20, 20, 20]
    float* out = (float*)d_out;                   // [N, 2]

    int N = in_sizes[0] / N_DIM;
    int ntiles = N / (4 * THREADS);               // 64 for N=32768

    prep_kernel<<<(394800 + 255) / 256, 256>>>(meanw0, meanw, varw0, varw);

    cudaFuncSetAttribute(main_kernel, cudaFuncAttributeMaxDynamicSharedMemorySize,
                         SMEM_BYTES);
    main_kernel<<<P_DIM * 7 * ntiles, THREADS, SMEM_BYTES>>>(X, perm, ntiles);

    reduce_kernel<<<(N + 255) / 256, 256>>>(out, N);
}